// round 3
// baseline (speedup 1.0000x reference)
#include <cuda_runtime.h>
#include <cstdint>
#include <cstddef>

// Problem constants
constexpr int HIDC  = 1024;
constexpr int SEQ   = 1024;
constexpr int NBAT  = 2;
constexpr int NHEAD = 16;
constexpr int HDIM  = 64;
constexpr int CACHE = 3072;
constexpr int TKV   = 4096;
constexpr int MTOT  = NBAT * SEQ;          // 2048 rows
constexpr size_t PLANE = (size_t)MTOT * HIDC;   // 2,097,152

// Output offsets (floats)
constexpr size_t OFF_OUT_RE = 0;
constexpr size_t OFF_OUT_IM = 2097152;
constexpr size_t OFF_K_RE   = 4194304;
constexpr size_t OFF_K_IM   = 12582912;
constexpr size_t OFF_V_RE   = 20971520;
constexpr size_t OFF_V_IM   = 29360128;

// Scratch (device globals — allocation-free)
__device__ float g_nr[PLANE];
__device__ float g_ni[PLANE];
__device__ float g_qr[PLANE];
__device__ float g_qi[PLANE];
__device__ float g_ar[PLANE];
__device__ float g_ai[PLANE];

// ---------------- tf32 helpers ----------------
__device__ __forceinline__ unsigned f2tf(float x) {
    unsigned r; asm("cvt.rna.tf32.f32 %0, %1;" : "=r"(r) : "f"(x)); return r;
}
__device__ __forceinline__ float tfb(float x) { return __uint_as_float(f2tf(x)); }

__device__ __forceinline__ void mma8(float* c, const unsigned* a, const unsigned* b) {
    asm("mma.sync.aligned.m16n8k8.row.col.f32.tf32.tf32.f32 "
        "{%0,%1,%2,%3},{%4,%5,%6,%7},{%8,%9},{%0,%1,%2,%3};"
        : "+f"(c[0]), "+f"(c[1]), "+f"(c[2]), "+f"(c[3])
        : "r"(a[0]), "r"(a[1]), "r"(a[2]), "r"(a[3]), "r"(b[0]), "r"(b[1]));
}

// ---------------- Complex LayerNorm ----------------
__global__ void ln_kernel(const float* __restrict__ hr, const float* __restrict__ hi,
                          const float* __restrict__ gamma,
                          const float* __restrict__ betar, const float* __restrict__ betai,
                          float* __restrict__ nr, float* __restrict__ ni) {
    int row = blockIdx.x;
    int tid = threadIdx.x, lane = tid & 31, wid = tid >> 5;
    const float* pr = hr + (size_t)row * HIDC;
    const float* pi = hi + (size_t)row * HIDC;

    float vr[4], vi[4];
    float sr = 0.f, si = 0.f, sq = 0.f;
#pragma unroll
    for (int j = 0; j < 4; j++) {
        int e = tid + j * 256;
        vr[j] = pr[e]; vi[j] = pi[e];
        sr += vr[j]; si += vi[j]; sq += vr[j] * vr[j] + vi[j] * vi[j];
    }
#pragma unroll
    for (int o = 16; o; o >>= 1) {
        sr += __shfl_xor_sync(0xffffffffu, sr, o);
        si += __shfl_xor_sync(0xffffffffu, si, o);
        sq += __shfl_xor_sync(0xffffffffu, sq, o);
    }
    __shared__ float red[3][8];
    if (lane == 0) { red[0][wid] = sr; red[1][wid] = si; red[2][wid] = sq; }
    __syncthreads();
    float tsr = 0.f, tsi = 0.f, tsq = 0.f;
#pragma unroll
    for (int w = 0; w < 8; w++) { tsr += red[0][w]; tsi += red[1][w]; tsq += red[2][w]; }
    float mur = tsr * (1.0f / HIDC);
    float mui = tsi * (1.0f / HIDC);
    float var = tsq * (1.0f / HIDC) - mur * mur - mui * mui;
    float inv = rsqrtf(var + 1e-5f);
#pragma unroll
    for (int j = 0; j < 4; j++) {
        int e = tid + j * 256;
        float gm = gamma[e] * inv;
        nr[(size_t)row * HIDC + e] = (vr[j] - mur) * gm + betar[e];
        ni[(size_t)row * HIDC + e] = (vi[j] - mui) * gm + betai[e];
    }
}

// ---------------- Complex projection GEMM ----------------
// yr[m,n] = sum_k xr[m,k]Wr[n,k] - xi[m,k]Wi[n,k] + br[n]  (+ resid)
// yi[m,n] = sum_k xr[m,k]Wi[n,k] + xi[m,k]Wr[n,k] + bi[n]  (+ resid)
// Folded K=2048: phase1 A=xr, Br=Wr, Bi=Wi; phase2 A=xi, Br=-Wi, Bi=Wr.
// Block 128x64, 8 warps (4m x 2n), warp 32x32, BK=32.
__global__ void __launch_bounds__(256, 1)
proj_kernel(const float* __restrict__ Ar, const float* __restrict__ Ai,
            const float* __restrict__ Wr, const float* __restrict__ Wi,
            const float* __restrict__ brp, const float* __restrict__ bip,
            float* __restrict__ Or, float* __restrict__ Oi,
            int kv_mode, const float* __restrict__ Rr, const float* __restrict__ Ri) {
    __shared__ float As[128 * 36];
    __shared__ float Brs[64 * 36];
    __shared__ float Bis[64 * 36];

    int tid = threadIdx.x, lane = tid & 31, wid = tid >> 5;
    int wm = wid & 3, wn = wid >> 2;
    int g = lane >> 2, t4 = lane & 3;
    int n0 = blockIdx.x * 64;
    int m0 = blockIdx.y * 128;

    float accR[2][4][4];
    float accI[2][4][4];
#pragma unroll
    for (int a = 0; a < 2; a++)
#pragma unroll
        for (int b = 0; b < 4; b++)
#pragma unroll
            for (int c = 0; c < 4; c++) { accR[a][b][c] = 0.f; accI[a][b][c] = 0.f; }

    for (int kk = 0; kk < 2048; kk += 32) {
        bool ph2 = kk >= 1024;
        const float* Ap  = ph2 ? Ai : Ar;
        const float* Wbr = ph2 ? Wi : Wr;
        const float* Wbi = ph2 ? Wr : Wi;
        float sgn = ph2 ? -1.f : 1.f;
        int ko = ph2 ? kk - 1024 : kk;

#pragma unroll
        for (int i = 0; i < 4; i++) {
            int slot = tid + i * 256;
            int r = slot >> 3, c = (slot & 7) * 4;
            float4 v = *reinterpret_cast<const float4*>(Ap + (size_t)(m0 + r) * HIDC + ko + c);
            float* d = &As[r * 36 + c];
            d[0] = tfb(v.x); d[1] = tfb(v.y); d[2] = tfb(v.z); d[3] = tfb(v.w);
        }
#pragma unroll
        for (int i = 0; i < 2; i++) {
            int slot = tid + i * 256;
            int r = slot >> 3, c = (slot & 7) * 4;
            float4 v = *reinterpret_cast<const float4*>(Wbr + (size_t)(n0 + r) * HIDC + ko + c);
            float* d = &Brs[r * 36 + c];
            d[0] = tfb(sgn * v.x); d[1] = tfb(sgn * v.y); d[2] = tfb(sgn * v.z); d[3] = tfb(sgn * v.w);
            float4 u = *reinterpret_cast<const float4*>(Wbi + (size_t)(n0 + r) * HIDC + ko + c);
            float* e = &Bis[r * 36 + c];
            e[0] = tfb(u.x); e[1] = tfb(u.y); e[2] = tfb(u.z); e[3] = tfb(u.w);
        }
        __syncthreads();

#pragma unroll
        for (int kb = 0; kb < 4; kb++) {
            unsigned a[2][4];
#pragma unroll
            for (int mt = 0; mt < 2; mt++) {
                int rb = wm * 32 + mt * 16;
                a[mt][0] = __float_as_uint(As[(rb + g) * 36 + kb * 8 + t4]);
                a[mt][1] = __float_as_uint(As[(rb + g + 8) * 36 + kb * 8 + t4]);
                a[mt][2] = __float_as_uint(As[(rb + g) * 36 + kb * 8 + t4 + 4]);
                a[mt][3] = __float_as_uint(As[(rb + g + 8) * 36 + kb * 8 + t4 + 4]);
            }
#pragma unroll
            for (int nt = 0; nt < 4; nt++) {
                int nb = wn * 32 + nt * 8 + g;
                unsigned bR[2] = { __float_as_uint(Brs[nb * 36 + kb * 8 + t4]),
                                   __float_as_uint(Brs[nb * 36 + kb * 8 + t4 + 4]) };
                unsigned bI[2] = { __float_as_uint(Bis[nb * 36 + kb * 8 + t4]),
                                   __float_as_uint(Bis[nb * 36 + kb * 8 + t4 + 4]) };
#pragma unroll
                for (int mt = 0; mt < 2; mt++) {
                    mma8(accR[mt][nt], a[mt], bR);
                    mma8(accI[mt][nt], a[mt], bI);
                }
            }
        }
        __syncthreads();
    }

    // epilogue
#pragma unroll
    for (int mt = 0; mt < 2; mt++) {
        int r0 = m0 + wm * 32 + mt * 16 + g;
        int r1 = r0 + 8;
        size_t or0, or1;
        if (kv_mode) {
            or0 = (size_t)((r0 >> 10) * TKV + CACHE + (r0 & 1023));
            or1 = (size_t)((r1 >> 10) * TKV + CACHE + (r1 & 1023));
        } else { or0 = (size_t)r0; or1 = (size_t)r1; }
#pragma unroll
        for (int nt = 0; nt < 4; nt++) {
            int c0 = n0 + wn * 32 + nt * 8 + 2 * t4;
            float vr0 = accR[mt][nt][0] + brp[c0];
            float vr1 = accR[mt][nt][1] + brp[c0 + 1];
            float vr2 = accR[mt][nt][2] + brp[c0];
            float vr3 = accR[mt][nt][3] + brp[c0 + 1];
            float vi0 = accI[mt][nt][0] + bip[c0];
            float vi1 = accI[mt][nt][1] + bip[c0 + 1];
            float vi2 = accI[mt][nt][2] + bip[c0];
            float vi3 = accI[mt][nt][3] + bip[c0 + 1];
            if (Rr) {
                vr0 += Rr[(size_t)r0 * HIDC + c0];     vr1 += Rr[(size_t)r0 * HIDC + c0 + 1];
                vr2 += Rr[(size_t)r1 * HIDC + c0];     vr3 += Rr[(size_t)r1 * HIDC + c0 + 1];
                vi0 += Ri[(size_t)r0 * HIDC + c0];     vi1 += Ri[(size_t)r0 * HIDC + c0 + 1];
                vi2 += Ri[(size_t)r1 * HIDC + c0];     vi3 += Ri[(size_t)r1 * HIDC + c0 + 1];
            }
            Or[or0 * HIDC + c0] = vr0;  Or[or0 * HIDC + c0 + 1] = vr1;
            Or[or1 * HIDC + c0] = vr2;  Or[or1 * HIDC + c0 + 1] = vr3;
            Oi[or0 * HIDC + c0] = vi0;  Oi[or0 * HIDC + c0 + 1] = vi1;
            Oi[or1 * HIDC + c0] = vi2;  Oi[or1 * HIDC + c0 + 1] = vi3;
        }
    }
}

// ---------------- Flash attention (qdim=128 concat, vdim=128 concat) ----------------
// grid: (S/128, B*NH), 256 threads (8 warps, each owning 16 query rows).
// Dynamic smem layout (floats): Qs[128][132] | Ks[64][132] | Vs[64][132] | Ps[8][16][68]
constexpr int QS_W = 16896;
constexpr int KS_W = QS_W + 8448;      // 25344
constexpr int PS_W = KS_W + 8448;      // 33792
constexpr int SMEM_WORDS = PS_W + 8704; // 42496 -> 169984 bytes

__global__ void __launch_bounds__(256, 1)
attn_kernel(const float* __restrict__ qr, const float* __restrict__ qi,
            const float* __restrict__ kr, const float* __restrict__ ki,
            const float* __restrict__ vr, const float* __restrict__ vi,
            float* __restrict__ ar, float* __restrict__ ai) {
    extern __shared__ float sm[];
    float* Qs = sm;
    float* Ks = sm + QS_W;
    float* Vs = sm + KS_W;
    float* Ps = sm + PS_W;

    int tid = threadIdx.x, lane = tid & 31, wid = tid >> 5;
    int g = lane >> 2, t4 = lane & 3;
    int q0 = blockIdx.x * 128;
    int b = blockIdx.y >> 4, h = blockIdx.y & 15;
    int wq = wid * 16;

    // load Q tile [128 q rows x 128 (r|i)]
#pragma unroll
    for (int it = 0; it < 16; it++) {
        int slot = tid + it * 256;
        int row = slot >> 5, cp = slot & 31;
        const float* src = (cp < 16) ? qr : qi;
        int d = (cp & 15) * 4;
        float4 v = *reinterpret_cast<const float4*>(
            src + ((size_t)(b * SEQ + q0 + row) * HIDC + h * 64 + d));
        float* dst = &Qs[row * 132 + cp * 4];
        dst[0] = tfb(v.x); dst[1] = tfb(v.y); dst[2] = tfb(v.z); dst[3] = tfb(v.w);
    }
    __syncthreads();

    float mrow[2] = { -1e30f, -1e30f };
    float lrow[2] = { 0.f, 0.f };
    float o[16][4];
#pragma unroll
    for (int nt = 0; nt < 16; nt++) { o[nt][0] = o[nt][1] = o[nt][2] = o[nt][3] = 0.f; }

    int t_end = min(TKV, q0 + 3200);
    float* pw = Ps + wid * (16 * 68);

    for (int t0 = 0; t0 < t_end; t0 += 64) {
        // load K,V tiles [64 keys x 128 (r|i)]
#pragma unroll
        for (int it = 0; it < 8; it++) {
            int slot = tid + it * 256;
            int row = slot >> 5, cp = slot & 31;
            size_t base = (size_t)(b * TKV + t0 + row) * HIDC + h * 64 + (cp & 15) * 4;
            float4 kv4 = *reinterpret_cast<const float4*>(((cp < 16) ? kr : ki) + base);
            float* dk = &Ks[row * 132 + cp * 4];
            dk[0] = tfb(kv4.x); dk[1] = tfb(kv4.y); dk[2] = tfb(kv4.z); dk[3] = tfb(kv4.w);
            float4 vv4 = *reinterpret_cast<const float4*>(((cp < 16) ? vr : vi) + base);
            float* dv = &Vs[row * 132 + cp * 4];
            dv[0] = tfb(vv4.x); dv[1] = tfb(vv4.y); dv[2] = tfb(vv4.z); dv[3] = tfb(vv4.w);
        }
        __syncthreads();

        // S = Q K^T  (warp: 16 x 64 over k=128)
        float s[8][4];
#pragma unroll
        for (int nt = 0; nt < 8; nt++) { s[nt][0] = s[nt][1] = s[nt][2] = s[nt][3] = 0.f; }
#pragma unroll
        for (int kb = 0; kb < 16; kb++) {
            unsigned a[4];
            a[0] = __float_as_uint(Qs[(wq + g) * 132 + kb * 8 + t4]);
            a[1] = __float_as_uint(Qs[(wq + g + 8) * 132 + kb * 8 + t4]);
            a[2] = __float_as_uint(Qs[(wq + g) * 132 + kb * 8 + t4 + 4]);
            a[3] = __float_as_uint(Qs[(wq + g + 8) * 132 + kb * 8 + t4 + 4]);
#pragma unroll
            for (int nt = 0; nt < 8; nt++) {
                unsigned bb[2] = { __float_as_uint(Ks[(nt * 8 + g) * 132 + kb * 8 + t4]),
                                   __float_as_uint(Ks[(nt * 8 + g) * 132 + kb * 8 + t4 + 4]) };
                mma8(s[nt], a, bb);
            }
        }

        // scale + mask
        bool needmask = (t0 + 63 > q0 + CACHE);
        int rg0 = q0 + wq + g, rg1 = rg0 + 8;
#pragma unroll
        for (int nt = 0; nt < 8; nt++) {
            s[nt][0] *= 0.125f; s[nt][1] *= 0.125f; s[nt][2] *= 0.125f; s[nt][3] *= 0.125f;
            if (needmask) {
                int c0 = t0 + nt * 8 + 2 * t4;
                if (c0     > rg0 + CACHE) s[nt][0] = -1e30f;
                if (c0 + 1 > rg0 + CACHE) s[nt][1] = -1e30f;
                if (c0     > rg1 + CACHE) s[nt][2] = -1e30f;
                if (c0 + 1 > rg1 + CACHE) s[nt][3] = -1e30f;
            }
        }

        // online softmax
        float mx0 = -1e30f, mx1 = -1e30f;
#pragma unroll
        for (int nt = 0; nt < 8; nt++) {
            mx0 = fmaxf(mx0, fmaxf(s[nt][0], s[nt][1]));
            mx1 = fmaxf(mx1, fmaxf(s[nt][2], s[nt][3]));
        }
        mx0 = fmaxf(mx0, __shfl_xor_sync(0xffffffffu, mx0, 1));
        mx0 = fmaxf(mx0, __shfl_xor_sync(0xffffffffu, mx0, 2));
        mx1 = fmaxf(mx1, __shfl_xor_sync(0xffffffffu, mx1, 1));
        mx1 = fmaxf(mx1, __shfl_xor_sync(0xffffffffu, mx1, 2));
        float mn0 = fmaxf(mrow[0], mx0), mn1 = fmaxf(mrow[1], mx1);
        float al0 = __expf(mrow[0] - mn0), al1 = __expf(mrow[1] - mn1);
        float rs0 = 0.f, rs1 = 0.f;
#pragma unroll
        for (int nt = 0; nt < 8; nt++) {
            s[nt][0] = __expf(s[nt][0] - mn0);
            s[nt][1] = __expf(s[nt][1] - mn0);
            s[nt][2] = __expf(s[nt][2] - mn1);
            s[nt][3] = __expf(s[nt][3] - mn1);
            rs0 += s[nt][0] + s[nt][1];
            rs1 += s[nt][2] + s[nt][3];
        }
        rs0 += __shfl_xor_sync(0xffffffffu, rs0, 1);
        rs0 += __shfl_xor_sync(0xffffffffu, rs0, 2);
        rs1 += __shfl_xor_sync(0xffffffffu, rs1, 1);
        rs1 += __shfl_xor_sync(0xffffffffu, rs1, 2);
        lrow[0] = lrow[0] * al0 + rs0;
        lrow[1] = lrow[1] * al1 + rs1;
        mrow[0] = mn0; mrow[1] = mn1;
#pragma unroll
        for (int nt = 0; nt < 16; nt++) {
            o[nt][0] *= al0; o[nt][1] *= al0; o[nt][2] *= al1; o[nt][3] *= al1;
        }

        // write P to warp-private smem (tf32) for the PV mma A operand
#pragma unroll
        for (int nt = 0; nt < 8; nt++) {
            int c = nt * 8 + 2 * t4;
            pw[g * 68 + c]           = tfb(s[nt][0]);
            pw[g * 68 + c + 1]       = tfb(s[nt][1]);
            pw[(g + 8) * 68 + c]     = tfb(s[nt][2]);
            pw[(g + 8) * 68 + c + 1] = tfb(s[nt][3]);
        }
        __syncwarp();

        // O += P @ V  (warp: 16 x 128 over k=64)
#pragma unroll
        for (int kb = 0; kb < 8; kb++) {
            unsigned a[4];
            a[0] = __float_as_uint(pw[g * 68 + kb * 8 + t4]);
            a[1] = __float_as_uint(pw[(g + 8) * 68 + kb * 8 + t4]);
            a[2] = __float_as_uint(pw[g * 68 + kb * 8 + t4 + 4]);
            a[3] = __float_as_uint(pw[(g + 8) * 68 + kb * 8 + t4 + 4]);
#pragma unroll
            for (int nt = 0; nt < 16; nt++) {
                unsigned bb[2] = { __float_as_uint(Vs[(kb * 8 + t4) * 132 + nt * 8 + g]),
                                   __float_as_uint(Vs[(kb * 8 + t4 + 4) * 132 + nt * 8 + g]) };
                mma8(o[nt], a, bb);
            }
        }
        __syncthreads();
    }

    // epilogue
    float il0 = 1.0f / lrow[0], il1 = 1.0f / lrow[1];
    int r0 = q0 + wq + g, r1 = r0 + 8;
    size_t rb0 = (size_t)(b * SEQ + r0) * HIDC + h * 64;
    size_t rb1 = (size_t)(b * SEQ + r1) * HIDC + h * 64;
#pragma unroll
    for (int nt = 0; nt < 16; nt++) {
        int d0 = nt * 8 + 2 * t4;
        float* dst = (d0 < 64) ? ar : ai;
        int dd = (d0 < 64) ? d0 : d0 - 64;
        dst[rb0 + dd]     = o[nt][0] * il0;
        dst[rb0 + dd + 1] = o[nt][1] * il0;
        dst[rb1 + dd]     = o[nt][2] * il1;
        dst[rb1 + dd + 1] = o[nt][3] * il1;
    }
}

// ---------------- launcher ----------------
extern "C" void kernel_launch(void* const* d_in, const int* in_sizes, int n_in,
                              void* d_out, int out_size) {
    const float* hr    = (const float*)d_in[0];
    const float* hi    = (const float*)d_in[1];
    const float* Kcr   = (const float*)d_in[2];
    const float* Kci   = (const float*)d_in[3];
    const float* Vcr   = (const float*)d_in[4];
    const float* Vci   = (const float*)d_in[5];
    const float* gamma = (const float*)d_in[6];
    const float* betar = (const float*)d_in[7];
    const float* betai = (const float*)d_in[8];
    const float* qWr = (const float*)d_in[9],  *qWi = (const float*)d_in[10];
    const float* qbr = (const float*)d_in[11], *qbi = (const float*)d_in[12];
    const float* kWr = (const float*)d_in[13], *kWi = (const float*)d_in[14];
    const float* kbr = (const float*)d_in[15], *kbi = (const float*)d_in[16];
    const float* vWr = (const float*)d_in[17], *vWi = (const float*)d_in[18];
    const float* vbr = (const float*)d_in[19], *vbi = (const float*)d_in[20];
    const float* oWr = (const float*)d_in[21], *oWi = (const float*)d_in[22];
    const float* obr = (const float*)d_in[23], *obi = (const float*)d_in[24];

    float* out = (float*)d_out;
    float* outR = out + OFF_OUT_RE;
    float* outI = out + OFF_OUT_IM;
    float* nKr  = out + OFF_K_RE;
    float* nKi  = out + OFF_K_IM;
    float* nVr  = out + OFF_V_RE;
    float* nVi  = out + OFF_V_IM;

    float *nr, *ni, *qr, *qi, *ar, *ai;
    cudaGetSymbolAddress((void**)&nr, g_nr);
    cudaGetSymbolAddress((void**)&ni, g_ni);
    cudaGetSymbolAddress((void**)&qr, g_qr);
    cudaGetSymbolAddress((void**)&qi, g_qi);
    cudaGetSymbolAddress((void**)&ar, g_ar);
    cudaGetSymbolAddress((void**)&ai, g_ai);

    // cache prefix copies: new_K/V[:, :3072] = caches
    for (int b = 0; b < NBAT; b++) {
        size_t dofs = (size_t)b * TKV * HIDC;
        size_t sofs = (size_t)b * CACHE * HIDC;
        size_t bytes = (size_t)CACHE * HIDC * sizeof(float);
        cudaMemcpyAsync(nKr + dofs, Kcr + sofs, bytes, cudaMemcpyDeviceToDevice, 0);
        cudaMemcpyAsync(nKi + dofs, Kci + sofs, bytes, cudaMemcpyDeviceToDevice, 0);
        cudaMemcpyAsync(nVr + dofs, Vcr + sofs, bytes, cudaMemcpyDeviceToDevice, 0);
        cudaMemcpyAsync(nVi + dofs, Vci + sofs, bytes, cudaMemcpyDeviceToDevice, 0);
    }

    ln_kernel<<<MTOT, 256>>>(hr, hi, gamma, betar, betai, nr, ni);

    dim3 pg(HIDC / 64, MTOT / 128);  // (16, 16)
    proj_kernel<<<pg, 256>>>(nr, ni, qWr, qWi, qbr, qbi, qr, qi, 0, nullptr, nullptr);
    proj_kernel<<<pg, 256>>>(nr, ni, kWr, kWi, kbr, kbi, nKr, nKi, 1, nullptr, nullptr);
    proj_kernel<<<pg, 256>>>(nr, ni, vWr, vWi, vbr, vbi, nVr, nVi, 1, nullptr, nullptr);

    cudaFuncSetAttribute(attn_kernel, cudaFuncAttributeMaxDynamicSharedMemorySize,
                         SMEM_WORDS * (int)sizeof(float));
    attn_kernel<<<dim3(SEQ / 128, NBAT * NHEAD), 256, SMEM_WORDS * sizeof(float)>>>(
        qr, qi, nKr, nKi, nVr, nVi, ar, ai);

    proj_kernel<<<pg, 256>>>(ar, ai, oWr, oWi, obr, obi, outR, outI, 0, hr, hi);
}

// round 4
// speedup vs baseline: 1.4601x; 1.4601x over previous
#include <cuda_runtime.h>
#include <cstdint>
#include <cstddef>

// Problem constants
constexpr int HIDC  = 1024;
constexpr int SEQ   = 1024;
constexpr int NBAT  = 2;
constexpr int NHEAD = 16;
constexpr int CACHE = 3072;
constexpr int TKV   = 4096;
constexpr int MTOT  = NBAT * SEQ;               // 2048 rows
constexpr size_t PLANE = (size_t)MTOT * HIDC;   // 2,097,152

// Output offsets (floats)
constexpr size_t OFF_OUT_RE = 0;
constexpr size_t OFF_OUT_IM = 2097152;
constexpr size_t OFF_K_RE   = 4194304;
constexpr size_t OFF_K_IM   = 12582912;
constexpr size_t OFF_V_RE   = 20971520;
constexpr size_t OFF_V_IM   = 29360128;

// Scratch (device globals — allocation-free)
__device__ float g_nr[PLANE];
__device__ float g_ni[PLANE];
__device__ float g_qr[PLANE];
__device__ float g_qi[PLANE];
__device__ float g_ar[PLANE];
__device__ float g_ai[PLANE];
__device__ float g_w[8u * 1024u * 1024u];   // rounded weights: qWr,qWi,kWr,kWi,vWr,vWi,oWr,oWi

// ---------------- tf32 / async helpers ----------------
__device__ __forceinline__ unsigned f2tf(float x) {
    unsigned r; asm("cvt.rna.tf32.f32 %0, %1;" : "=r"(r) : "f"(x)); return r;
}
__device__ __forceinline__ float tfb(float x) { return __uint_as_float(f2tf(x)); }
__device__ __forceinline__ unsigned u32(float x) { return __float_as_uint(x); }

__device__ __forceinline__ void mma8(float* c, const unsigned* a, const unsigned* b) {
    asm("mma.sync.aligned.m16n8k8.row.col.f32.tf32.tf32.f32 "
        "{%0,%1,%2,%3},{%4,%5,%6,%7},{%8,%9},{%0,%1,%2,%3};"
        : "+f"(c[0]), "+f"(c[1]), "+f"(c[2]), "+f"(c[3])
        : "r"(a[0]), "r"(a[1]), "r"(a[2]), "r"(a[3]), "r"(b[0]), "r"(b[1]));
}

__device__ __forceinline__ void cpa16(unsigned dst, const void* src) {
    asm volatile("cp.async.cg.shared.global [%0], [%1], 16;" :: "r"(dst), "l"(src) : "memory");
}
__device__ __forceinline__ void cpcommit() {
    asm volatile("cp.async.commit_group;" ::: "memory");
}
__device__ __forceinline__ void cpwait1() {
    asm volatile("cp.async.wait_group 1;" ::: "memory");
}
__device__ __forceinline__ void cpwait0() {
    asm volatile("cp.async.wait_group 0;" ::: "memory");
}

// ---------------- round-copy (weights + cache prefix) ----------------
__global__ void copy_round_kernel(const float4* __restrict__ src, float4* __restrict__ dst, int n4) {
    int i = blockIdx.x * blockDim.x + threadIdx.x;
    if (i < n4) {
        float4 v = src[i];
        dst[i] = make_float4(tfb(v.x), tfb(v.y), tfb(v.z), tfb(v.w));
    }
}

// ---------------- Complex LayerNorm (outputs rounded to tf32 grid) ----------------
__global__ void ln_kernel(const float* __restrict__ hr, const float* __restrict__ hi,
                          const float* __restrict__ gamma,
                          const float* __restrict__ betar, const float* __restrict__ betai,
                          float* __restrict__ nr, float* __restrict__ ni) {
    int row = blockIdx.x;
    int tid = threadIdx.x, lane = tid & 31, wid = tid >> 5;
    const float* pr = hr + (size_t)row * HIDC;
    const float* pi = hi + (size_t)row * HIDC;

    float vr[4], vi[4];
    float sr = 0.f, si = 0.f, sq = 0.f;
#pragma unroll
    for (int j = 0; j < 4; j++) {
        int e = tid + j * 256;
        vr[j] = pr[e]; vi[j] = pi[e];
        sr += vr[j]; si += vi[j]; sq += vr[j] * vr[j] + vi[j] * vi[j];
    }
#pragma unroll
    for (int o = 16; o; o >>= 1) {
        sr += __shfl_xor_sync(0xffffffffu, sr, o);
        si += __shfl_xor_sync(0xffffffffu, si, o);
        sq += __shfl_xor_sync(0xffffffffu, sq, o);
    }
    __shared__ float red[3][8];
    if (lane == 0) { red[0][wid] = sr; red[1][wid] = si; red[2][wid] = sq; }
    __syncthreads();
    float tsr = 0.f, tsi = 0.f, tsq = 0.f;
#pragma unroll
    for (int w = 0; w < 8; w++) { tsr += red[0][w]; tsi += red[1][w]; tsq += red[2][w]; }
    float mur = tsr * (1.0f / HIDC);
    float mui = tsi * (1.0f / HIDC);
    float var = tsq * (1.0f / HIDC) - mur * mur - mui * mui;
    float inv = rsqrtf(var + 1e-5f);
#pragma unroll
    for (int j = 0; j < 4; j++) {
        int e = tid + j * 256;
        float gm = gamma[e] * inv;
        nr[(size_t)row * HIDC + e] = tfb((vr[j] - mur) * gm + betar[e]);
        ni[(size_t)row * HIDC + e] = tfb((vi[j] - mui) * gm + betai[e]);
    }
}

// ---------------- Complex projection GEMM v2 ----------------
// Folded K=2048: phase1 A=xr: accR += a*Wr, accI += a*Wi
//                phase2 A=xi: accR += (-a)*Wi, accI += a*Wr
// Block 128x64 out (R and I), 8 warps (4m x 2n), warp 32x32, BK=32.
// Double-buffered cp.async; LDS.64 pair loads under a consistent k-permutation.
constexpr int PJ_SA   = 40;                 // padded row stride in floats
constexpr int PJ_ASZ  = 128 * PJ_SA;        // 5120 floats
constexpr int PJ_BSZ  = 64 * PJ_SA;         // 2560 floats
constexpr int PJ_SMEM = (2 * PJ_ASZ + 4 * PJ_BSZ) * 4;   // 81920 bytes

__global__ void __launch_bounds__(256, 2)
proj_kernel(const float* __restrict__ Ar, const float* __restrict__ Ai,
            const float* __restrict__ Wr, const float* __restrict__ Wi,
            const float* __restrict__ brp, const float* __restrict__ bip,
            float* __restrict__ Or, float* __restrict__ Oi,
            int kv_mode, int round_out,
            const float* __restrict__ Rr, const float* __restrict__ Ri) {
    extern __shared__ float sm[];
    float* As  = sm;                     // [2][PJ_ASZ]
    float* Brs = sm + 2 * PJ_ASZ;        // [2][PJ_BSZ]
    float* Bis = Brs + 2 * PJ_BSZ;       // [2][PJ_BSZ]
    unsigned sbase = (unsigned)__cvta_generic_to_shared(sm);

    int tid = threadIdx.x, lane = tid & 31, wid = tid >> 5;
    int wm = wid & 3, wn = wid >> 2;
    int g = lane >> 2, t4 = lane & 3;
    int n0 = blockIdx.x * 64;
    int m0 = blockIdx.y * 128;

    float accR[2][4][4];
    float accI[2][4][4];
#pragma unroll
    for (int a = 0; a < 2; a++)
#pragma unroll
        for (int b = 0; b < 4; b++)
#pragma unroll
            for (int c = 0; c < 4; c++) { accR[a][b][c] = 0.f; accI[a][b][c] = 0.f; }

    // ---- issue for iteration `it` (32 k at a time) ----
    auto issue = [&](int it) {
        int kk = it * 32;
        int ko = kk & 1023;
        const float* Ap = (kk >= 1024) ? Ai : Ar;
        int buf = it & 1;
#pragma unroll
        for (int i = 0; i < 4; i++) {
            int id = tid + i * 256;
            int r = id >> 3, c = id & 7;
            cpa16(sbase + (unsigned)(buf * PJ_ASZ + r * PJ_SA + c * 4) * 4u,
                  Ap + (size_t)(m0 + r) * HIDC + ko + c * 4);
        }
#pragma unroll
        for (int i = 0; i < 2; i++) {
            int id = tid + i * 256;
            int r = id >> 3, c = id & 7;
            size_t go = (size_t)(n0 + r) * HIDC + ko + c * 4;
            cpa16(sbase + (unsigned)(2 * PJ_ASZ + buf * PJ_BSZ + r * PJ_SA + c * 4) * 4u, Wr + go);
            cpa16(sbase + (unsigned)(2 * PJ_ASZ + 2 * PJ_BSZ + buf * PJ_BSZ + r * PJ_SA + c * 4) * 4u, Wi + go);
        }
        cpcommit();
    };

    issue(0);
    issue(1);

    for (int it = 0; it < 64; it++) {
        if (it < 63) cpwait1(); else cpwait0();
        __syncthreads();

        int buf = it & 1;
        bool ph2 = (it >= 32);
        const float* Ab = As + buf * PJ_ASZ;
        const float* Bb = Brs + buf * PJ_BSZ;
        const float* Cb = Bis + buf * PJ_BSZ;

#pragma unroll
        for (int kb = 0; kb < 4; kb++) {
            unsigned a[2][4], na[2][4];
#pragma unroll
            for (int mt = 0; mt < 2; mt++) {
                int rb = wm * 32 + mt * 16;
                float2 x = *reinterpret_cast<const float2*>(Ab + (rb + g) * PJ_SA + kb * 8 + 2 * t4);
                float2 y = *reinterpret_cast<const float2*>(Ab + (rb + g + 8) * PJ_SA + kb * 8 + 2 * t4);
                a[mt][0] = u32(x.x); a[mt][1] = u32(y.x); a[mt][2] = u32(x.y); a[mt][3] = u32(y.y);
                if (ph2) {
                    na[mt][0] = a[mt][0] ^ 0x80000000u; na[mt][1] = a[mt][1] ^ 0x80000000u;
                    na[mt][2] = a[mt][2] ^ 0x80000000u; na[mt][3] = a[mt][3] ^ 0x80000000u;
                }
            }
#pragma unroll
            for (int nt = 0; nt < 4; nt++) {
                int nb = wn * 32 + nt * 8 + g;
                float2 r2 = *reinterpret_cast<const float2*>(Bb + nb * PJ_SA + kb * 8 + 2 * t4);
                float2 i2 = *reinterpret_cast<const float2*>(Cb + nb * PJ_SA + kb * 8 + 2 * t4);
                unsigned bR[2] = { u32(r2.x), u32(r2.y) };
                unsigned bI[2] = { u32(i2.x), u32(i2.y) };
                if (ph2) {
#pragma unroll
                    for (int mt = 0; mt < 2; mt++) {
                        mma8(accR[mt][nt], na[mt], bI);
                        mma8(accI[mt][nt], a[mt], bR);
                    }
                } else {
#pragma unroll
                    for (int mt = 0; mt < 2; mt++) {
                        mma8(accR[mt][nt], a[mt], bR);
                        mma8(accI[mt][nt], a[mt], bI);
                    }
                }
            }
        }
        __syncthreads();
        if (it + 2 < 64) issue(it + 2);
    }

    // epilogue
#pragma unroll
    for (int mt = 0; mt < 2; mt++) {
        int r0 = m0 + wm * 32 + mt * 16 + g;
        int r1 = r0 + 8;
        size_t or0, or1;
        if (kv_mode) {
            or0 = (size_t)((r0 >> 10) * TKV + CACHE + (r0 & 1023));
            or1 = (size_t)((r1 >> 10) * TKV + CACHE + (r1 & 1023));
        } else { or0 = (size_t)r0; or1 = (size_t)r1; }
#pragma unroll
        for (int nt = 0; nt < 4; nt++) {
            int c0 = n0 + wn * 32 + nt * 8 + 2 * t4;
            float vr0 = accR[mt][nt][0] + brp[c0];
            float vr1 = accR[mt][nt][1] + brp[c0 + 1];
            float vr2 = accR[mt][nt][2] + brp[c0];
            float vr3 = accR[mt][nt][3] + brp[c0 + 1];
            float vi0 = accI[mt][nt][0] + bip[c0];
            float vi1 = accI[mt][nt][1] + bip[c0 + 1];
            float vi2 = accI[mt][nt][2] + bip[c0];
            float vi3 = accI[mt][nt][3] + bip[c0 + 1];
            if (Rr) {
                vr0 += Rr[(size_t)r0 * HIDC + c0];     vr1 += Rr[(size_t)r0 * HIDC + c0 + 1];
                vr2 += Rr[(size_t)r1 * HIDC + c0];     vr3 += Rr[(size_t)r1 * HIDC + c0 + 1];
                vi0 += Ri[(size_t)r0 * HIDC + c0];     vi1 += Ri[(size_t)r0 * HIDC + c0 + 1];
                vi2 += Ri[(size_t)r1 * HIDC + c0];     vi3 += Ri[(size_t)r1 * HIDC + c0 + 1];
            }
            if (round_out) {
                vr0 = tfb(vr0); vr1 = tfb(vr1); vr2 = tfb(vr2); vr3 = tfb(vr3);
                vi0 = tfb(vi0); vi1 = tfb(vi1); vi2 = tfb(vi2); vi3 = tfb(vi3);
            }
            Or[or0 * HIDC + c0] = vr0;  Or[or0 * HIDC + c0 + 1] = vr1;
            Or[or1 * HIDC + c0] = vr2;  Or[or1 * HIDC + c0 + 1] = vr3;
            Oi[or0 * HIDC + c0] = vi0;  Oi[or0 * HIDC + c0 + 1] = vi1;
            Oi[or1 * HIDC + c0] = vi2;  Oi[or1 * HIDC + c0 + 1] = vi3;
        }
    }
}

// ---------------- Flash attention v2 ----------------
// grid: (S/128, B*NH), 256 threads (8 warps x 16 q rows).
// Double-buffered cp.async K/V; Q via cp.async once; P kept in registers
// (QK C-fragment maps onto PV A-fragment under a kv permutation matched by
// reading V rows kb*8+2t4, kb*8+2t4+1).
constexpr int AQ_S = 136;
constexpr int AK_S = 136;
constexpr int AV_S = 132;
constexpr int Q_SZ = 128 * AQ_S;   // 17408 floats
constexpr int K_SZ = 64 * AK_S;    // 8704
constexpr int V_SZ = 64 * AV_S;    // 8448
constexpr int AT_SMEM = (Q_SZ + 2 * K_SZ + 2 * V_SZ) * 4;  // 206848 bytes

__global__ void __launch_bounds__(256, 1)
attn_kernel(const float* __restrict__ qr, const float* __restrict__ qi,
            const float* __restrict__ kr, const float* __restrict__ ki,
            const float* __restrict__ vr, const float* __restrict__ vi,
            float* __restrict__ ar, float* __restrict__ ai) {
    extern __shared__ float sm[];
    float* Qs = sm;
    unsigned sbase = (unsigned)__cvta_generic_to_shared(sm);

    int tid = threadIdx.x, lane = tid & 31, wid = tid >> 5;
    int g = lane >> 2, t4 = lane & 3;
    int q0 = blockIdx.x * 128;
    int b = blockIdx.y >> 4, h = blockIdx.y & 15;
    int wq = wid * 16;

    int t_end = min(TKV, q0 + 3200);
    int nIter = t_end / 64;

    // Q tile via cp.async (part of group 0)
#pragma unroll
    for (int i = 0; i < 16; i++) {
        int id = tid + i * 256;
        int r = id >> 5, c = id & 31;
        const float* src = ((c < 16) ? qr : qi) + (size_t)(b * SEQ + q0 + r) * HIDC + h * 64 + (c & 15) * 4;
        cpa16(sbase + (unsigned)(r * AQ_S + c * 4) * 4u, src);
    }

    auto issueKV = [&](int it) {
        int t0 = it * 64;
        int buf = it & 1;
#pragma unroll
        for (int i = 0; i < 8; i++) {
            int id = tid + i * 256;
            int r = id >> 5, c = id & 31;
            size_t gb = (size_t)(b * TKV + t0 + r) * HIDC + h * 64 + (c & 15) * 4;
            cpa16(sbase + (unsigned)((Q_SZ + buf * K_SZ) + r * AK_S + c * 4) * 4u,
                  ((c < 16) ? kr : ki) + gb);
            cpa16(sbase + (unsigned)((Q_SZ + 2 * K_SZ + buf * V_SZ) + r * AV_S + c * 4) * 4u,
                  ((c < 16) ? vr : vi) + gb);
        }
        cpcommit();
    };

    issueKV(0);                    // group 0 = Q + KV0
    if (nIter > 1) issueKV(1);     // group 1

    float mrow[2] = { -1e30f, -1e30f };
    float lrow[2] = { 0.f, 0.f };
    float o[16][4];
#pragma unroll
    for (int nt = 0; nt < 16; nt++) { o[nt][0] = o[nt][1] = o[nt][2] = o[nt][3] = 0.f; }

    for (int it = 0; it < nIter; it++) {
        if (it + 1 < nIter) cpwait1(); else cpwait0();
        __syncthreads();

        int t0 = it * 64;
        int buf = it & 1;
        const float* Kb = sm + Q_SZ + buf * K_SZ;
        const float* Vb = sm + Q_SZ + 2 * K_SZ + buf * V_SZ;

        // S = Q K^T  (warp: 16 x 64, k=128, pair-permuted LDS.64)
        float s[8][4];
#pragma unroll
        for (int nt = 0; nt < 8; nt++) { s[nt][0] = s[nt][1] = s[nt][2] = s[nt][3] = 0.f; }
#pragma unroll
        for (int kb = 0; kb < 16; kb++) {
            float2 x = *reinterpret_cast<const float2*>(Qs + (wq + g) * AQ_S + kb * 8 + 2 * t4);
            float2 y = *reinterpret_cast<const float2*>(Qs + (wq + g + 8) * AQ_S + kb * 8 + 2 * t4);
            unsigned a[4] = { u32(x.x), u32(y.x), u32(x.y), u32(y.y) };
#pragma unroll
            for (int nt = 0; nt < 8; nt++) {
                float2 k2 = *reinterpret_cast<const float2*>(Kb + (nt * 8 + g) * AK_S + kb * 8 + 2 * t4);
                unsigned bb[2] = { u32(k2.x), u32(k2.y) };
                mma8(s[nt], a, bb);
            }
        }

        // scale + mask
        bool needmask = (t0 + 63 > q0 + CACHE);
        int rg0 = q0 + wq + g, rg1 = rg0 + 8;
#pragma unroll
        for (int nt = 0; nt < 8; nt++) {
            s[nt][0] *= 0.125f; s[nt][1] *= 0.125f; s[nt][2] *= 0.125f; s[nt][3] *= 0.125f;
            if (needmask) {
                int c0 = t0 + nt * 8 + 2 * t4;
                if (c0     > rg0 + CACHE) s[nt][0] = -1e30f;
                if (c0 + 1 > rg0 + CACHE) s[nt][1] = -1e30f;
                if (c0     > rg1 + CACHE) s[nt][2] = -1e30f;
                if (c0 + 1 > rg1 + CACHE) s[nt][3] = -1e30f;
            }
        }

        // online softmax
        float mx0 = -1e30f, mx1 = -1e30f;
#pragma unroll
        for (int nt = 0; nt < 8; nt++) {
            mx0 = fmaxf(mx0, fmaxf(s[nt][0], s[nt][1]));
            mx1 = fmaxf(mx1, fmaxf(s[nt][2], s[nt][3]));
        }
        mx0 = fmaxf(mx0, __shfl_xor_sync(0xffffffffu, mx0, 1));
        mx0 = fmaxf(mx0, __shfl_xor_sync(0xffffffffu, mx0, 2));
        mx1 = fmaxf(mx1, __shfl_xor_sync(0xffffffffu, mx1, 1));
        mx1 = fmaxf(mx1, __shfl_xor_sync(0xffffffffu, mx1, 2));
        float mn0 = fmaxf(mrow[0], mx0), mn1 = fmaxf(mrow[1], mx1);
        float al0 = __expf(mrow[0] - mn0), al1 = __expf(mrow[1] - mn1);
        float rs0 = 0.f, rs1 = 0.f;
#pragma unroll
        for (int nt = 0; nt < 8; nt++) {
            s[nt][0] = __expf(s[nt][0] - mn0);
            s[nt][1] = __expf(s[nt][1] - mn0);
            s[nt][2] = __expf(s[nt][2] - mn1);
            s[nt][3] = __expf(s[nt][3] - mn1);
            rs0 += s[nt][0] + s[nt][1];
            rs1 += s[nt][2] + s[nt][3];
        }
        rs0 += __shfl_xor_sync(0xffffffffu, rs0, 1);
        rs0 += __shfl_xor_sync(0xffffffffu, rs0, 2);
        rs1 += __shfl_xor_sync(0xffffffffu, rs1, 1);
        rs1 += __shfl_xor_sync(0xffffffffu, rs1, 2);
        lrow[0] = lrow[0] * al0 + rs0;
        lrow[1] = lrow[1] * al1 + rs1;
        mrow[0] = mn0; mrow[1] = mn1;
#pragma unroll
        for (int nt = 0; nt < 16; nt++) {
            o[nt][0] *= al0; o[nt][1] *= al0; o[nt][2] *= al1; o[nt][3] *= al1;
        }

        // O += P @ V  — P in registers (rounded to tf32); V rows kb*8+2t4, +1
#pragma unroll
        for (int kb = 0; kb < 8; kb++) {
            unsigned a[4] = { f2tf(s[kb][0]), f2tf(s[kb][2]), f2tf(s[kb][1]), f2tf(s[kb][3]) };
            const float* v0p = Vb + (kb * 8 + 2 * t4) * AV_S;
            const float* v1p = v0p + AV_S;
#pragma unroll
            for (int nt = 0; nt < 16; nt++) {
                int n = nt * 8 + g;
                unsigned bb[2] = { u32(v0p[n]), u32(v1p[n]) };
                mma8(o[nt], a, bb);
            }
        }
        __syncthreads();
        if (it + 2 < nIter) issueKV(it + 2);
    }

    // epilogue — round so the O-projection's tf32 inputs are exact
    float il0 = 1.0f / lrow[0], il1 = 1.0f / lrow[1];
    int r0 = q0 + wq + g, r1 = r0 + 8;
    size_t rb0 = (size_t)(b * SEQ + r0) * HIDC + h * 64;
    size_t rb1 = (size_t)(b * SEQ + r1) * HIDC + h * 64;
#pragma unroll
    for (int nt = 0; nt < 16; nt++) {
        int d0 = nt * 8 + 2 * t4;
        float* dst = (d0 < 64) ? ar : ai;
        int dd = (d0 < 64) ? d0 : d0 - 64;
        dst[rb0 + dd]     = tfb(o[nt][0] * il0);
        dst[rb0 + dd + 1] = tfb(o[nt][1] * il0);
        dst[rb1 + dd]     = tfb(o[nt][2] * il1);
        dst[rb1 + dd + 1] = tfb(o[nt][3] * il1);
    }
}

// ---------------- launcher ----------------
extern "C" void kernel_launch(void* const* d_in, const int* in_sizes, int n_in,
                              void* d_out, int out_size) {
    const float* hr    = (const float*)d_in[0];
    const float* hi    = (const float*)d_in[1];
    const float* Kcr   = (const float*)d_in[2];
    const float* Kci   = (const float*)d_in[3];
    const float* Vcr   = (const float*)d_in[4];
    const float* Vci   = (const float*)d_in[5];
    const float* gamma = (const float*)d_in[6];
    const float* betar = (const float*)d_in[7];
    const float* betai = (const float*)d_in[8];
    const float* Wsrc[8] = {
        (const float*)d_in[9],  (const float*)d_in[10],   // qWr, qWi
        (const float*)d_in[13], (const float*)d_in[14],   // kWr, kWi
        (const float*)d_in[17], (const float*)d_in[18],   // vWr, vWi
        (const float*)d_in[21], (const float*)d_in[22]    // oWr, oWi
    };
    const float* qbr = (const float*)d_in[11], *qbi = (const float*)d_in[12];
    const float* kbr = (const float*)d_in[15], *kbi = (const float*)d_in[16];
    const float* vbr = (const float*)d_in[19], *vbi = (const float*)d_in[20];
    const float* obr = (const float*)d_in[23], *obi = (const float*)d_in[24];

    float* out = (float*)d_out;
    float* outR = out + OFF_OUT_RE;
    float* outI = out + OFF_OUT_IM;
    float* nKr  = out + OFF_K_RE;
    float* nKi  = out + OFF_K_IM;
    float* nVr  = out + OFF_V_RE;
    float* nVi  = out + OFF_V_IM;

    float *nr, *ni, *qr, *qi, *ar, *ai, *wbuf;
    cudaGetSymbolAddress((void**)&nr, g_nr);
    cudaGetSymbolAddress((void**)&ni, g_ni);
    cudaGetSymbolAddress((void**)&qr, g_qr);
    cudaGetSymbolAddress((void**)&qi, g_qi);
    cudaGetSymbolAddress((void**)&ar, g_ar);
    cudaGetSymbolAddress((void**)&ai, g_ai);
    cudaGetSymbolAddress((void**)&wbuf, g_w);

    cudaFuncSetAttribute(proj_kernel, cudaFuncAttributeMaxDynamicSharedMemorySize, PJ_SMEM);
    cudaFuncSetAttribute(attn_kernel, cudaFuncAttributeMaxDynamicSharedMemorySize, AT_SMEM);

    // round weights into scratch (tf32-exact mma inputs)
    constexpr size_t WPLANE = 1024u * 1024u;
    for (int i = 0; i < 8; i++) {
        copy_round_kernel<<<(int)(WPLANE / 4 / 256), 256>>>(
            (const float4*)Wsrc[i], (float4*)(wbuf + (size_t)i * WPLANE), (int)(WPLANE / 4));
    }

    // cache prefix: rounded copy into output K/V head (also the attention source)
    {
        int n4 = CACHE * HIDC / 4;  // per batch
        int gsz = n4 / 256;
        for (int b = 0; b < NBAT; b++) {
            size_t dofs = (size_t)b * TKV * HIDC;
            size_t sofs = (size_t)b * CACHE * HIDC;
            copy_round_kernel<<<gsz, 256>>>((const float4*)(Kcr + sofs), (float4*)(nKr + dofs), n4);
            copy_round_kernel<<<gsz, 256>>>((const float4*)(Kci + sofs), (float4*)(nKi + dofs), n4);
            copy_round_kernel<<<gsz, 256>>>((const float4*)(Vcr + sofs), (float4*)(nVr + dofs), n4);
            copy_round_kernel<<<gsz, 256>>>((const float4*)(Vci + sofs), (float4*)(nVi + dofs), n4);
        }
    }

    ln_kernel<<<MTOT, 256>>>(hr, hi, gamma, betar, betai, nr, ni);

    dim3 pg(HIDC / 64, MTOT / 128);  // (16, 16)
    proj_kernel<<<pg, 256, PJ_SMEM>>>(nr, ni, wbuf + 0 * WPLANE, wbuf + 1 * WPLANE,
                                      qbr, qbi, qr, qi, 0, 1, nullptr, nullptr);
    proj_kernel<<<pg, 256, PJ_SMEM>>>(nr, ni, wbuf + 2 * WPLANE, wbuf + 3 * WPLANE,
                                      kbr, kbi, nKr, nKi, 1, 1, nullptr, nullptr);
    proj_kernel<<<pg, 256, PJ_SMEM>>>(nr, ni, wbuf + 4 * WPLANE, wbuf + 5 * WPLANE,
                                      vbr, vbi, nVr, nVi, 1, 1, nullptr, nullptr);

    attn_kernel<<<dim3(SEQ / 128, NBAT * NHEAD), 256, AT_SMEM>>>(
        qr, qi, nKr, nKi, nVr, nVi, ar, ai);

    proj_kernel<<<pg, 256, PJ_SMEM>>>(ar, ai, wbuf + 6 * WPLANE, wbuf + 7 * WPLANE,
                                      obr, obi, outR, outI, 0, 0, hr, hi);
}